// round 3
// baseline (speedup 1.0000x reference)
#include <cuda_runtime.h>

#define HW (1024 * 1024)
#define NB 16
#define BLOCKS_PER_BATCH 128
#define NBLOCKS (NB * BLOCKS_PER_BATCH)   // 2048
#define THREADS 128
#define EPS 1e-6f

// per-block partial sums: {S_p, S_pp, S_tp, S_t}
__device__ float4 g_partials[NBLOCKS];
__device__ unsigned int g_count = 0;   // self-resetting; 0 before/after every launch

__device__ __forceinline__ void accum(float l0, float l1, int t,
                                      float& sp, float& spp, float& stp, float& st) {
    // p1 = sigmoid(l1 - l0) = 0.5*tanh(0.5*(l1-l0)) + 0.5  (single MUFU.TANH)
    float x = l1 - l0;
    float p = 0.5f * tanhf(0.5f * x) + 0.5f;
    float tf = (t != 0) ? 1.0f : 0.0f;
    sp  += p;
    spp += p * p;
    stp += tf * p;
    st  += tf;
}

__global__ __launch_bounds__(THREADS)
void dice_fused_kernel(const float* __restrict__ logits,
                       const int* __restrict__ labels,
                       float* __restrict__ out) {
    const int b   = blockIdx.x / BLOCKS_PER_BATCH;
    const int blk = blockIdx.x % BLOCKS_PER_BATCH;

    const float4* __restrict__ l0v = (const float4*)(logits + (size_t)b * 2 * HW);
    const float4* __restrict__ l1v = (const float4*)(logits + (size_t)b * 2 * HW + HW);
    const int4*   __restrict__ tv  = (const int4*)(labels + (size_t)b * HW);

    const int n4        = HW / 4;                  // 262144 float4 per plane
    const int per_block = n4 / BLOCKS_PER_BATCH;   // 2048
    const int base      = blk * per_block;

    float sp = 0.f, spp = 0.f, stp = 0.f, st = 0.f;

#pragma unroll 4
    for (int i = threadIdx.x; i < per_block; i += THREADS) {
        float4 a = __ldcs(&l0v[base + i]);
        float4 c = __ldcs(&l1v[base + i]);
        int4   t = __ldcs(&tv[base + i]);
        accum(a.x, c.x, t.x, sp, spp, stp, st);
        accum(a.y, c.y, t.y, sp, spp, stp, st);
        accum(a.z, c.z, t.z, sp, spp, stp, st);
        accum(a.w, c.w, t.w, sp, spp, stp, st);
    }

    // block reduce to one float4
#pragma unroll
    for (int o = 16; o > 0; o >>= 1) {
        sp  += __shfl_down_sync(0xFFFFFFFFu, sp, o);
        spp += __shfl_down_sync(0xFFFFFFFFu, spp, o);
        stp += __shfl_down_sync(0xFFFFFFFFu, stp, o);
        st  += __shfl_down_sync(0xFFFFFFFFu, st, o);
    }

    __shared__ float4 sh[THREADS / 32];
    __shared__ bool   amLast;
    const int wid  = threadIdx.x >> 5;
    const int lane = threadIdx.x & 31;
    if (lane == 0) sh[wid] = make_float4(sp, spp, stp, st);
    __syncthreads();

    if (wid == 0) {
        float4 v = (lane < THREADS / 32) ? sh[lane] : make_float4(0.f, 0.f, 0.f, 0.f);
#pragma unroll
        for (int o = 2; o > 0; o >>= 1) {
            v.x += __shfl_down_sync(0xFFFFFFFFu, v.x, o);
            v.y += __shfl_down_sync(0xFFFFFFFFu, v.y, o);
            v.z += __shfl_down_sync(0xFFFFFFFFu, v.z, o);
            v.w += __shfl_down_sync(0xFFFFFFFFu, v.w, o);
        }
        if (lane == 0) {
            g_partials[blockIdx.x] = v;
            __threadfence();
            unsigned int prev = atomicAdd(&g_count, 1u);
            amLast = (prev == NBLOCKS - 1);
        }
    }
    __syncthreads();

    // ---- last block does the final reduction ----
    if (amLast) {
        __shared__ float dice[NB];
        // 4 warps, 16 batches: warp w handles batches 4w..4w+3
#pragma unroll
        for (int r = 0; r < 4; r++) {
            const int bb = wid * 4 + r;
            float fsp = 0.f, fspp = 0.f, fstp = 0.f, fst = 0.f;
#pragma unroll
            for (int j = 0; j < BLOCKS_PER_BATCH / 32; j++) {
                float4 a = __ldcg(&g_partials[bb * BLOCKS_PER_BATCH + j * 32 + lane]);
                fsp  += a.x;
                fspp += a.y;
                fstp += a.z;
                fst  += a.w;
            }
#pragma unroll
            for (int o = 16; o > 0; o >>= 1) {
                fsp  += __shfl_down_sync(0xFFFFFFFFu, fsp, o);
                fspp += __shfl_down_sync(0xFFFFFFFFu, fspp, o);
                fstp += __shfl_down_sync(0xFFFFFFFFu, fstp, o);
                fst  += __shfl_down_sync(0xFFFFFFFFu, fst, o);
            }
            if (lane == 0) {
                const float N = (float)HW;
                // channel 1
                float num1 = 2.0f * fstp;
                float den1 = fspp + fst;          // t^2 = t
                // channel 0 (p0 = 1-p1, t0 = 1-t1)
                float num0 = 2.0f * (N - fst - fsp + fstp);
                float den0 = (N - 2.0f * fsp + fspp) + (N - fst);
                dice[bb] = num1 / (den1 + EPS) + num0 / (den0 + EPS);
            }
        }
        __syncthreads();
        if (threadIdx.x == 0) {
            float s = 0.f;
#pragma unroll
            for (int i = 0; i < NB; i++) s += dice[i];
            out[0] = 1.0f - s / (float)(2 * NB);
            g_count = 0;   // reset for next (graph-replayed) launch
        }
    }
}

extern "C" void kernel_launch(void* const* d_in, const int* in_sizes, int n_in,
                              void* d_out, int out_size) {
    const float* logits = (const float*)d_in[0];
    const int*   labels = (const int*)d_in[1];
    float*       out    = (float*)d_out;

    dice_fused_kernel<<<NBLOCKS, THREADS>>>(logits, labels, out);
}

// round 4
// speedup vs baseline: 1.1981x; 1.1981x over previous
#include <cuda_runtime.h>

#define HW (1024 * 1024)
#define NB 16
#define BLOCKS_PER_BATCH 64
#define NBLOCKS (NB * BLOCKS_PER_BATCH)   // 1024
#define THREADS 256
#define EPS 1e-6f

// per-block partial sums: {S_p, S_pp, S_tp, S_t}
__device__ float4 g_partials[NBLOCKS];
__device__ unsigned int g_count = 0;   // self-resetting; 0 before/after every launch

__device__ __forceinline__ void accum(float l0, float l1, int t,
                                      float& sp, float& spp, float& stp, float& st) {
    // p1 = sigmoid(l1 - l0) = 1 / (1 + exp(l0 - l1))
    float e = __expf(l0 - l1);
    float p = __fdividef(1.0f, 1.0f + e);
    float tf = (t != 0) ? 1.0f : 0.0f;
    sp  += p;
    spp += p * p;
    stp += tf * p;
    st  += tf;
}

__global__ __launch_bounds__(THREADS, 8)
void dice_fused_kernel(const float* __restrict__ logits,
                       const int* __restrict__ labels,
                       float* __restrict__ out) {
    const int b   = blockIdx.x / BLOCKS_PER_BATCH;
    const int blk = blockIdx.x % BLOCKS_PER_BATCH;

    const float4* __restrict__ l0v = (const float4*)(logits + (size_t)b * 2 * HW);
    const float4* __restrict__ l1v = (const float4*)(logits + (size_t)b * 2 * HW + HW);
    const int4*   __restrict__ tv  = (const int4*)(labels + (size_t)b * HW);

    const int n4        = HW / 4;                  // 262144 float4 per plane
    const int per_block = n4 / BLOCKS_PER_BATCH;   // 4096
    const int base      = blk * per_block;

    float sp = 0.f, spp = 0.f, stp = 0.f, st = 0.f;

#pragma unroll 4
    for (int i = threadIdx.x; i < per_block; i += THREADS) {
        float4 a = l0v[base + i];
        float4 c = l1v[base + i];
        int4   t = tv[base + i];
        accum(a.x, c.x, t.x, sp, spp, stp, st);
        accum(a.y, c.y, t.y, sp, spp, stp, st);
        accum(a.z, c.z, t.z, sp, spp, stp, st);
        accum(a.w, c.w, t.w, sp, spp, stp, st);
    }

    // block reduce to one float4
#pragma unroll
    for (int o = 16; o > 0; o >>= 1) {
        sp  += __shfl_down_sync(0xFFFFFFFFu, sp, o);
        spp += __shfl_down_sync(0xFFFFFFFFu, spp, o);
        stp += __shfl_down_sync(0xFFFFFFFFu, stp, o);
        st  += __shfl_down_sync(0xFFFFFFFFu, st, o);
    }

    __shared__ float4 sh[THREADS / 32];
    __shared__ bool   amLast;
    const int wid  = threadIdx.x >> 5;
    const int lane = threadIdx.x & 31;
    if (lane == 0) sh[wid] = make_float4(sp, spp, stp, st);
    __syncthreads();

    if (wid == 0) {
        float4 v = (lane < THREADS / 32) ? sh[lane] : make_float4(0.f, 0.f, 0.f, 0.f);
#pragma unroll
        for (int o = 4; o > 0; o >>= 1) {
            v.x += __shfl_down_sync(0xFFFFFFFFu, v.x, o);
            v.y += __shfl_down_sync(0xFFFFFFFFu, v.y, o);
            v.z += __shfl_down_sync(0xFFFFFFFFu, v.z, o);
            v.w += __shfl_down_sync(0xFFFFFFFFu, v.w, o);
        }
        if (lane == 0) {
            g_partials[blockIdx.x] = v;
            __threadfence();
            unsigned int prev = atomicAdd(&g_count, 1u);
            amLast = (prev == NBLOCKS - 1);
        }
    }
    __syncthreads();

    // ---- last block does the final reduction ----
    if (amLast) {
        __shared__ float dice[NB];
        // 8 warps, 16 batches: warp w handles batches 2w and 2w+1
#pragma unroll
        for (int r = 0; r < 2; r++) {
            const int bb = wid * 2 + r;
            float4 a = __ldcg(&g_partials[bb * BLOCKS_PER_BATCH + lane]);
            float4 c = __ldcg(&g_partials[bb * BLOCKS_PER_BATCH + 32 + lane]);
            float fsp  = a.x + c.x;
            float fspp = a.y + c.y;
            float fstp = a.z + c.z;
            float fst  = a.w + c.w;
#pragma unroll
            for (int o = 16; o > 0; o >>= 1) {
                fsp  += __shfl_down_sync(0xFFFFFFFFu, fsp, o);
                fspp += __shfl_down_sync(0xFFFFFFFFu, fspp, o);
                fstp += __shfl_down_sync(0xFFFFFFFFu, fstp, o);
                fst  += __shfl_down_sync(0xFFFFFFFFu, fst, o);
            }
            if (lane == 0) {
                const float N = (float)HW;
                // channel 1
                float num1 = 2.0f * fstp;
                float den1 = fspp + fst;          // t^2 = t
                // channel 0 (p0 = 1-p1, t0 = 1-t1)
                float num0 = 2.0f * (N - fst - fsp + fstp);
                float den0 = (N - 2.0f * fsp + fspp) + (N - fst);
                dice[bb] = num1 / (den1 + EPS) + num0 / (den0 + EPS);
            }
        }
        __syncthreads();
        if (threadIdx.x == 0) {
            float s = 0.f;
#pragma unroll
            for (int i = 0; i < NB; i++) s += dice[i];
            out[0] = 1.0f - s / (float)(2 * NB);
            g_count = 0;   // reset for next (graph-replayed) launch
        }
    }
}

extern "C" void kernel_launch(void* const* d_in, const int* in_sizes, int n_in,
                              void* d_out, int out_size) {
    const float* logits = (const float*)d_in[0];
    const int*   labels = (const int*)d_in[1];
    float*       out    = (float*)d_out;

    dice_fused_kernel<<<NBLOCKS, THREADS>>>(logits, labels, out);
}

// round 5
// speedup vs baseline: 1.1991x; 1.0009x over previous
#include <cuda_runtime.h>

#define HW (1024 * 1024)
#define N4 (HW / 4)                       // 262144 float4 per plane
#define NB 16
#define BLOCKS_PER_BATCH 74
#define NBLOCKS (NB * BLOCKS_PER_BATCH)   // 1184 = 148 SMs * 8 CTAs
#define THREADS 256
#define EPS 1e-6f

// per-block partial sums: {S_p, S_pp, S_tp, S_t}
__device__ float4 g_partials[NBLOCKS];
__device__ unsigned int g_count = 0;   // self-resetting; 0 before/after every launch

__device__ __forceinline__ void accum(float l0, float l1, int t,
                                      float& sp, float& spp, float& stp, float& st) {
    // p1 = sigmoid(l1 - l0) = 1 / (1 + exp(l0 - l1))
    float e = __expf(l0 - l1);
    float p = __fdividef(1.0f, 1.0f + e);
    float tf = (t != 0) ? 1.0f : 0.0f;
    sp  += p;
    spp += p * p;
    stp += tf * p;
    st  += tf;
}

__global__ __launch_bounds__(THREADS, 8)
void dice_fused_kernel(const float* __restrict__ logits,
                       const int* __restrict__ labels,
                       float* __restrict__ out) {
    const int b   = blockIdx.x / BLOCKS_PER_BATCH;
    const int blk = blockIdx.x % BLOCKS_PER_BATCH;

    const float4* __restrict__ l0v = (const float4*)(logits + (size_t)b * 2 * HW);
    const float4* __restrict__ l1v = (const float4*)(logits + (size_t)b * 2 * HW + HW);
    const int4*   __restrict__ tv  = (const int4*)(labels + (size_t)b * HW);

    // balanced split of N4 float4s over 74 blocks (ranges differ by <=1)
    const int start = (int)(((long long)blk       * N4) / BLOCKS_PER_BATCH);
    const int end   = (int)(((long long)(blk + 1) * N4) / BLOCKS_PER_BATCH);

    float sp = 0.f, spp = 0.f, stp = 0.f, st = 0.f;

#pragma unroll 4
    for (int i = start + threadIdx.x; i < end; i += THREADS) {
        float4 a = l0v[i];
        float4 c = l1v[i];
        int4   t = tv[i];
        accum(a.x, c.x, t.x, sp, spp, stp, st);
        accum(a.y, c.y, t.y, sp, spp, stp, st);
        accum(a.z, c.z, t.z, sp, spp, stp, st);
        accum(a.w, c.w, t.w, sp, spp, stp, st);
    }

    // block reduce to one float4
#pragma unroll
    for (int o = 16; o > 0; o >>= 1) {
        sp  += __shfl_down_sync(0xFFFFFFFFu, sp, o);
        spp += __shfl_down_sync(0xFFFFFFFFu, spp, o);
        stp += __shfl_down_sync(0xFFFFFFFFu, stp, o);
        st  += __shfl_down_sync(0xFFFFFFFFu, st, o);
    }

    __shared__ float4 sh[THREADS / 32];
    __shared__ bool   amLast;
    const int wid  = threadIdx.x >> 5;
    const int lane = threadIdx.x & 31;
    if (lane == 0) sh[wid] = make_float4(sp, spp, stp, st);
    __syncthreads();

    if (wid == 0) {
        float4 v = (lane < THREADS / 32) ? sh[lane] : make_float4(0.f, 0.f, 0.f, 0.f);
#pragma unroll
        for (int o = 4; o > 0; o >>= 1) {
            v.x += __shfl_down_sync(0xFFFFFFFFu, v.x, o);
            v.y += __shfl_down_sync(0xFFFFFFFFu, v.y, o);
            v.z += __shfl_down_sync(0xFFFFFFFFu, v.z, o);
            v.w += __shfl_down_sync(0xFFFFFFFFu, v.w, o);
        }
        if (lane == 0) {
            g_partials[blockIdx.x] = v;
            __threadfence();
            unsigned int prev = atomicAdd(&g_count, 1u);
            amLast = (prev == NBLOCKS - 1);
        }
    }
    __syncthreads();

    // ---- last block does the final reduction ----
    if (amLast) {
        __shared__ float dice[NB];
        // 8 warps, 16 batches: warp w handles batches 2w and 2w+1
#pragma unroll
        for (int r = 0; r < 2; r++) {
            const int bb = wid * 2 + r;
            float fsp = 0.f, fspp = 0.f, fstp = 0.f, fst = 0.f;
#pragma unroll
            for (int j = lane; j < BLOCKS_PER_BATCH; j += 32) {
                float4 a = __ldcg(&g_partials[bb * BLOCKS_PER_BATCH + j]);
                fsp  += a.x;
                fspp += a.y;
                fstp += a.z;
                fst  += a.w;
            }
#pragma unroll
            for (int o = 16; o > 0; o >>= 1) {
                fsp  += __shfl_down_sync(0xFFFFFFFFu, fsp, o);
                fspp += __shfl_down_sync(0xFFFFFFFFu, fspp, o);
                fstp += __shfl_down_sync(0xFFFFFFFFu, fstp, o);
                fst  += __shfl_down_sync(0xFFFFFFFFu, fst, o);
            }
            if (lane == 0) {
                const float N = (float)HW;
                // channel 1
                float num1 = 2.0f * fstp;
                float den1 = fspp + fst;          // t^2 = t
                // channel 0 (p0 = 1-p1, t0 = 1-t1)
                float num0 = 2.0f * (N - fst - fsp + fstp);
                float den0 = (N - 2.0f * fsp + fspp) + (N - fst);
                dice[bb] = num1 / (den1 + EPS) + num0 / (den0 + EPS);
            }
        }
        __syncthreads();
        if (threadIdx.x == 0) {
            float s = 0.f;
#pragma unroll
            for (int i = 0; i < NB; i++) s += dice[i];
            out[0] = 1.0f - s / (float)(2 * NB);
            g_count = 0;   // reset for next (graph-replayed) launch
        }
    }
}

extern "C" void kernel_launch(void* const* d_in, const int* in_sizes, int n_in,
                              void* d_out, int out_size) {
    const float* logits = (const float*)d_in[0];
    const int*   labels = (const int*)d_in[1];
    float*       out    = (float*)d_out;

    dice_fused_kernel<<<NBLOCKS, THREADS>>>(logits, labels, out);
}

// round 6
// speedup vs baseline: 1.2063x; 1.0060x over previous
#include <cuda_runtime.h>

#define HW (1024 * 1024)
#define N4 (HW / 4)                       // 262144 float4 per plane
#define NB 16
#define BLOCKS_PER_BATCH 56
#define NBLOCKS (NB * BLOCKS_PER_BATCH)   // 896 ~= 148 SMs * 6 CTAs
#define THREADS 256
#define EPS 1e-6f

// per-block partial sums: {S_p, S_pp, S_tp, S_t}
__device__ float4 g_partials[NBLOCKS];
__device__ unsigned int g_count = 0;   // self-resetting; 0 before/after every launch

__device__ __forceinline__ void accum(float l0, float l1, int t,
                                      float& sp, float& spp, float& stp, float& st) {
    // p1 = sigmoid(l1 - l0) = 1 / (1 + exp(l0 - l1))
    float e = __expf(l0 - l1);
    float p = __fdividef(1.0f, 1.0f + e);
    float tf = (t != 0) ? 1.0f : 0.0f;
    sp  += p;
    spp += p * p;
    stp += tf * p;
    st  += tf;
}

__global__ __launch_bounds__(THREADS, 6)
void dice_fused_kernel(const float* __restrict__ logits,
                       const int* __restrict__ labels,
                       float* __restrict__ out) {
    const int b   = blockIdx.x / BLOCKS_PER_BATCH;
    const int blk = blockIdx.x % BLOCKS_PER_BATCH;

    const float4* __restrict__ l0v = (const float4*)(logits + (size_t)b * 2 * HW);
    const float4* __restrict__ l1v = (const float4*)(logits + (size_t)b * 2 * HW + HW);
    const int4*   __restrict__ tv  = (const int4*)(labels + (size_t)b * HW);

    // balanced split of N4 float4s over blocks (ranges differ by <=1)
    const int start = (int)(((long long)blk       * N4) / BLOCKS_PER_BATCH);
    const int end   = (int)(((long long)(blk + 1) * N4) / BLOCKS_PER_BATCH);

    float sp = 0.f, spp = 0.f, stp = 0.f, st = 0.f;

    int i = start + threadIdx.x;

    // 2-deep software pipeline: keep next iteration's 3 vectors in flight
    float4 a0, c0;
    int4   t0;
    if (i < end) {
        a0 = l0v[i];
        c0 = l1v[i];
        t0 = tv[i];
    }
    for (; i < end; ) {
        const int inext = i + THREADS;
        float4 a1, c1;
        int4   t1;
        if (inext < end) {
            a1 = l0v[inext];
            c1 = l1v[inext];
            t1 = tv[inext];
        }
        accum(a0.x, c0.x, t0.x, sp, spp, stp, st);
        accum(a0.y, c0.y, t0.y, sp, spp, stp, st);
        accum(a0.z, c0.z, t0.z, sp, spp, stp, st);
        accum(a0.w, c0.w, t0.w, sp, spp, stp, st);
        a0 = a1; c0 = c1; t0 = t1;
        i = inext;
    }

    // block reduce to one float4
#pragma unroll
    for (int o = 16; o > 0; o >>= 1) {
        sp  += __shfl_down_sync(0xFFFFFFFFu, sp, o);
        spp += __shfl_down_sync(0xFFFFFFFFu, spp, o);
        stp += __shfl_down_sync(0xFFFFFFFFu, stp, o);
        st  += __shfl_down_sync(0xFFFFFFFFu, st, o);
    }

    __shared__ float4 sh[THREADS / 32];
    __shared__ bool   amLast;
    const int wid  = threadIdx.x >> 5;
    const int lane = threadIdx.x & 31;
    if (lane == 0) sh[wid] = make_float4(sp, spp, stp, st);
    __syncthreads();

    if (wid == 0) {
        float4 v = (lane < THREADS / 32) ? sh[lane] : make_float4(0.f, 0.f, 0.f, 0.f);
#pragma unroll
        for (int o = 4; o > 0; o >>= 1) {
            v.x += __shfl_down_sync(0xFFFFFFFFu, v.x, o);
            v.y += __shfl_down_sync(0xFFFFFFFFu, v.y, o);
            v.z += __shfl_down_sync(0xFFFFFFFFu, v.z, o);
            v.w += __shfl_down_sync(0xFFFFFFFFu, v.w, o);
        }
        if (lane == 0) {
            g_partials[blockIdx.x] = v;
            __threadfence();
            unsigned int prev = atomicAdd(&g_count, 1u);
            amLast = (prev == NBLOCKS - 1);
        }
    }
    __syncthreads();

    // ---- last block does the final reduction ----
    if (amLast) {
        __shared__ float dice[NB];
        // 8 warps, 16 batches: warp w handles batches 2w and 2w+1
#pragma unroll
        for (int r = 0; r < 2; r++) {
            const int bb = wid * 2 + r;
            float fsp = 0.f, fspp = 0.f, fstp = 0.f, fst = 0.f;
#pragma unroll
            for (int j = lane; j < BLOCKS_PER_BATCH; j += 32) {
                float4 a = __ldcg(&g_partials[bb * BLOCKS_PER_BATCH + j]);
                fsp  += a.x;
                fspp += a.y;
                fstp += a.z;
                fst  += a.w;
            }
#pragma unroll
            for (int o = 16; o > 0; o >>= 1) {
                fsp  += __shfl_down_sync(0xFFFFFFFFu, fsp, o);
                fspp += __shfl_down_sync(0xFFFFFFFFu, fspp, o);
                fstp += __shfl_down_sync(0xFFFFFFFFu, fstp, o);
                fst  += __shfl_down_sync(0xFFFFFFFFu, fst, o);
            }
            if (lane == 0) {
                const float N = (float)HW;
                // channel 1
                float num1 = 2.0f * fstp;
                float den1 = fspp + fst;          // t^2 = t
                // channel 0 (p0 = 1-p1, t0 = 1-t1)
                float num0 = 2.0f * (N - fst - fsp + fstp);
                float den0 = (N - 2.0f * fsp + fspp) + (N - fst);
                dice[bb] = num1 / (den1 + EPS) + num0 / (den0 + EPS);
            }
        }
        __syncthreads();
        if (threadIdx.x == 0) {
            float s = 0.f;
#pragma unroll
            for (int i2 = 0; i2 < NB; i2++) s += dice[i2];
            out[0] = 1.0f - s / (float)(2 * NB);
            g_count = 0;   // reset for next (graph-replayed) launch
        }
    }
}

extern "C" void kernel_launch(void* const* d_in, const int* in_sizes, int n_in,
                              void* d_out, int out_size) {
    const float* logits = (const float*)d_in[0];
    const int*   labels = (const int*)d_in[1];
    float*       out    = (float*)d_out;

    dice_fused_kernel<<<NBLOCKS, THREADS>>>(logits, labels, out);
}